// round 1
// baseline (speedup 1.0000x reference)
#include <cuda_runtime.h>
#include <cuda_bf16.h>

#define N_NODES 20000
#define N_EDGES 500000
#define BATCH   2
#define D       128
#define H       4
#define L       3
#define HD      (H*D)        // 512
#define LD      (L*D)        // 384
#define F       (L*H + 1)    // 13
#define SLOPE   0.2f

// ---------------- scratch (static device globals; no allocation) ----------------
__device__ float g_h[N_NODES * D];          // current node features (10.2 MB)
__device__ float g_hp[N_NODES * HD];        // per-layer projected features (41 MB)
__device__ float g_as[N_NODES * H];         // alpha_src scalars
__device__ float g_ad[N_NODES * H];         // alpha_dst scalars
__device__ float g_xacc[N_NODES * LD];      // concat of layer outputs (30.7 MB)
__device__ float g_ac[N_EDGES * (L * H)];   // per-edge attention coeffs (24 MB)
__device__ int   g_deg[N_NODES];
__device__ int   g_rowptr[N_NODES + 1];
__device__ int   g_cursor[N_NODES];
__device__ int   g_csr_src[N_EDGES];
__device__ int   g_csr_eid[N_EDGES];
__device__ float g_colsum[LD];

// ---------------- init / CSR build ----------------
__global__ void zero_kernel() {
    int i = blockIdx.x * blockDim.x + threadIdx.x;
    if (i < N_NODES) g_deg[i] = 0;
    if (i < LD)      g_colsum[i] = 0.f;
}

__global__ void hist_kernel(const int* __restrict__ dst) {
    int e = blockIdx.x * blockDim.x + threadIdx.x;
    if (e < N_EDGES) atomicAdd(&g_deg[dst[e]], 1);
}

__global__ void __launch_bounds__(1024) scan_kernel() {
    __shared__ int sh[1024];
    const int t = threadIdx.x;
    const int C = (N_NODES + 1023) / 1024;   // 20
    int start = t * C, end = min(start + C, N_NODES);
    int s = 0;
    for (int i = start; i < end; i++) s += g_deg[i];
    sh[t] = s;
    __syncthreads();
    for (int off = 1; off < 1024; off <<= 1) {
        int v = (t >= off) ? sh[t - off] : 0;
        __syncthreads();
        sh[t] += v;
        __syncthreads();
    }
    int run = sh[t] - s;   // exclusive prefix
    for (int i = start; i < end; i++) {
        g_rowptr[i] = run;
        g_cursor[i] = run;
        run += g_deg[i];
    }
    if (t == 1023) g_rowptr[N_NODES] = sh[1023];
}

__global__ void fill_kernel(const int* __restrict__ src, const int* __restrict__ dst) {
    int e = blockIdx.x * blockDim.x + threadIdx.x;
    if (e < N_EDGES) {
        int d = dst[e];
        int pos = atomicAdd(&g_cursor[d], 1);
        g_csr_src[pos] = src[e];
        g_csr_eid[pos] = e;
    }
}

// ---------------- SGEMM: C[M,N] = A[M,128] @ B, B[k][n] = Bp[k*ldbk + n*ldbn] ----------------
__global__ void __launch_bounds__(256) sgemm_kernel(
    const float* __restrict__ A, const float* __restrict__ B,
    float* __restrict__ C, const float* __restrict__ bias,
    int M, int N, int ldbk, int ldbn)
{
    const int BM = 64, BN = 64, BK = 16;
    __shared__ float As[BK][BM + 4];
    __shared__ float Bs[BK][BN];
    const int tid = threadIdx.x;
    const int bm = blockIdx.x * BM, bn = blockIdx.y * BN;
    const int tx = tid & 15, ty = tid >> 4;
    const int arow = tid >> 2, acol = (tid & 3) * 4;

    float acc[4][4] = {};

    for (int k0 = 0; k0 < 128; k0 += BK) {
        // load A tile (float4 per thread)
        int gr = bm + arow;
        float4 av = make_float4(0.f, 0.f, 0.f, 0.f);
        if (gr < M) av = *(const float4*)(A + gr * 128 + k0 + acol);
        As[acol + 0][arow] = av.x;
        As[acol + 1][arow] = av.y;
        As[acol + 2][arow] = av.z;
        As[acol + 3][arow] = av.w;
        // load B tile (4 scalar loads per thread)
        #pragma unroll
        for (int s = 0; s < 4; s++) {
            int i = tid + s * 256;
            int kk = i >> 6, nn = i & 63;
            int gn = bn + nn;
            Bs[kk][nn] = (gn < N) ? B[(k0 + kk) * ldbk + gn * ldbn] : 0.f;
        }
        __syncthreads();
        #pragma unroll
        for (int k = 0; k < BK; k++) {
            float ra[4], rb[4];
            #pragma unroll
            for (int i = 0; i < 4; i++) ra[i] = As[k][ty * 4 + i];
            #pragma unroll
            for (int j = 0; j < 4; j++) rb[j] = Bs[k][tx * 4 + j];
            #pragma unroll
            for (int i = 0; i < 4; i++)
                #pragma unroll
                for (int j = 0; j < 4; j++)
                    acc[i][j] += ra[i] * rb[j];
        }
        __syncthreads();
    }

    #pragma unroll
    for (int i = 0; i < 4; i++) {
        int r = bm + ty * 4 + i;
        if (r >= M) continue;
        #pragma unroll
        for (int j = 0; j < 4; j++) {
            int c = bn + tx * 4 + j;
            if (c < N) {
                float v = acc[i][j];
                if (bias) v += bias[c];
                C[r * N + c] = v;
            }
        }
    }
}

// ---------------- per-(node,head) attention scalars ----------------
__global__ void __launch_bounds__(128) scal_kernel(
    const float* __restrict__ a_s, const float* __restrict__ a_d)
{
    int n = blockIdx.x;
    int w = threadIdx.x >> 5, ln = threadIdx.x & 31;
    const float* hpn = g_hp + n * HD + w * D;
    float ss = 0.f, sd = 0.f;
    #pragma unroll
    for (int j = 0; j < 4; j++) {
        int c = ln + 32 * j;
        float v = hpn[c];
        ss += v * a_s[w * D + c];
        sd += v * a_d[w * D + c];
    }
    #pragma unroll
    for (int off = 16; off; off >>= 1) {
        ss += __shfl_xor_sync(0xffffffffu, ss, off);
        sd += __shfl_xor_sync(0xffffffffu, sd, off);
    }
    if (ln == 0) {
        g_as[n * H + w] = ss;
        g_ad[n * H + w] = sd;
    }
}

// ---------------- softmax + aggregation + head-mean + activation (one block/node) ----------------
__global__ void __launch_bounds__(128) agg_kernel(const float* __restrict__ b_l, int layer) {
    __shared__ float sh[HD];
    const int n = blockIdx.x;
    const int w = threadIdx.x >> 5, ln = threadIdx.x & 31;
    const int start = g_rowptr[n], end = g_rowptr[n + 1];
    const float ad_h = g_ad[n * H + w];

    // pass 1: local softmax denominator (no max-shift: e is bounded, exp safe)
    float sum_ex = 0.f;
    #pragma unroll 4
    for (int i = start; i < end; i++) {
        float ev = g_as[g_csr_src[i] * H + w] + ad_h;
        ev = ev > 0.f ? ev : SLOPE * ev;
        sum_ex += __expf(ev);
    }
    const float inv = 1.0f / (sum_ex + 1e-16f);

    // pass 2: weighted gather-accumulate
    float4 acc = make_float4(0.f, 0.f, 0.f, 0.f);
    #pragma unroll 2
    for (int i = start; i < end; i++) {
        int src = g_csr_src[i];
        float ev = g_as[src * H + w] + ad_h;
        ev = ev > 0.f ? ev : SLOPE * ev;
        float alpha = __expf(ev) * inv;
        float4 v = *(const float4*)(g_hp + src * HD + w * D + ln * 4);
        acc.x += alpha * v.x;
        acc.y += alpha * v.y;
        acc.z += alpha * v.z;
        acc.w += alpha * v.w;
        if (ln == 0) g_ac[g_csr_eid[i] * (L * H) + layer * H + w] = alpha;
    }
    *(float4*)&sh[w * D + ln * 4] = acc;
    __syncthreads();

    // head mean + bias -> xacc ; leaky_relu -> next-layer h
    int t = threadIdx.x;   // channel
    float v = 0.25f * (sh[t] + sh[D + t] + sh[2 * D + t] + sh[3 * D + t]) + b_l[t];
    g_xacc[n * LD + layer * D + t] = v;
    g_h[n * D + t] = v > 0.f ? v : SLOPE * v;
}

// ---------------- column means of xacc ----------------
__global__ void __launch_bounds__(LD) colmean_kernel() {
    int col = threadIdx.x;
    int n0 = blockIdx.x * 256, n1 = min(n0 + 256, N_NODES);
    float s = 0.f;
    for (int n = n0; n < n1; n++) s += g_xacc[n * LD + col];
    atomicAdd(&g_colsum[col], s);
}

// ---------------- row 0 of output (mean-node logits path) ----------------
__global__ void __launch_bounds__(128) row0_kernel(
    const float* __restrict__ W_xa, const float* __restrict__ b_xa,
    const float* __restrict__ W_r1, const float* __restrict__ b_r1,
    const float* __restrict__ W_r2, const float* __restrict__ b_r2,
    float* __restrict__ out)
{
    __shared__ float smean[LD];
    __shared__ float sxl[F];
    __shared__ float red[128];
    int t = threadIdx.x;
    for (int i = t; i < LD; i += 128) smean[i] = g_colsum[i] * (1.0f / N_NODES);
    __syncthreads();
    if (t < F) {
        float s = b_xa[t];
        for (int k = 0; k < LD; k++) s += smean[k] * W_xa[t * LD + k];
        sxl[t] = s;
    }
    __syncthreads();
    float hsum = b_r1[t];
    #pragma unroll
    for (int j = 0; j < F; j++) hsum += sxl[j] * W_r1[t * F + j];
    hsum = fmaxf(hsum, 0.f);
    red[t] = W_r2[t] * hsum;
    __syncthreads();
    for (int off = 64; off; off >>= 1) {
        if (t < off) red[t] += red[t + off];
        __syncthreads();
    }
    if (t == 0) {
        float v = red[0] + b_r2[0];
        out[0] = v;
        out[N_EDGES + 1] = v;
    }
}

// ---------------- per-edge readout (4 edges per block, 1 warp each) ----------------
__global__ void __launch_bounds__(128) readout_kernel(
    const float* __restrict__ state,
    const float* __restrict__ W_r1, const float* __restrict__ b_r1,
    const float* __restrict__ W_r2, const float* __restrict__ b_r2,
    float* __restrict__ out)
{
    __shared__ float sW1t[F * 128];   // transposed: [feature][channel]
    __shared__ float sb1[128];
    __shared__ float sW2[128];
    int t = threadIdx.x;
    #pragma unroll
    for (int j = 0; j < F; j++) sW1t[j * 128 + t] = W_r1[t * F + j];
    sb1[t] = b_r1[t];
    sW2[t] = W_r2[t];
    __syncthreads();
    float br2 = b_r2[0];

    int w = t >> 5, ln = t & 31;
    int e = blockIdx.x * 4 + w;
    if (e >= N_EDGES) return;
    int c = ln * 4;

    float u0 = sb1[c], u1 = sb1[c + 1], u2 = sb1[c + 2], u3 = sb1[c + 3];
    const float* ace = g_ac + (long)e * (L * H);
    #pragma unroll
    for (int j = 0; j < L * H; j++) {
        float a = ace[j];
        const float* wr = &sW1t[(j + 1) * 128 + c];
        u0 += a * wr[0]; u1 += a * wr[1]; u2 += a * wr[2]; u3 += a * wr[3];
    }
    float v0 = sW1t[c], v1 = sW1t[c + 1], v2 = sW1t[c + 2], v3 = sW1t[c + 3];
    float q0 = sW2[c], q1 = sW2[c + 1], q2 = sW2[c + 2], q3 = sW2[c + 3];

    #pragma unroll
    for (int b = 0; b < BATCH; b++) {
        float s = state[(long)b * N_EDGES + e];
        float p = q0 * fmaxf(u0 + s * v0, 0.f)
                + q1 * fmaxf(u1 + s * v1, 0.f)
                + q2 * fmaxf(u2 + s * v2, 0.f)
                + q3 * fmaxf(u3 + s * v3, 0.f);
        #pragma unroll
        for (int off = 16; off; off >>= 1) p += __shfl_xor_sync(0xffffffffu, p, off);
        if (ln == 0) out[(long)b * (N_EDGES + 1) + 1 + e] = p + br2;
    }
}

// ---------------- launch ----------------
extern "C" void kernel_launch(void* const* d_in, const int* in_sizes, int n_in,
                              void* d_out, int out_size)
{
    const float* state = (const float*)d_in[0];
    const int*   ei    = (const int*)d_in[1];
    const float* x     = (const float*)d_in[2];
    const float* W_in  = (const float*)d_in[3];
    const float* b_in  = (const float*)d_in[4];
    const float* W_l   = (const float*)d_in[5];
    const float* a_src = (const float*)d_in[6];
    const float* a_dst = (const float*)d_in[7];
    const float* b_l   = (const float*)d_in[8];
    const float* W_xa  = (const float*)d_in[9];
    const float* b_xa  = (const float*)d_in[10];
    const float* W_r1  = (const float*)d_in[11];
    const float* b_r1  = (const float*)d_in[12];
    const float* W_r2  = (const float*)d_in[13];
    const float* b_r2  = (const float*)d_in[14];
    float* out = (float*)d_out;

    const int* src = ei;
    const int* dst = ei + N_EDGES;

    float* hptr;  cudaGetSymbolAddress((void**)&hptr,  g_h);
    float* hpptr; cudaGetSymbolAddress((void**)&hpptr, g_hp);

    // CSR build
    zero_kernel<<<(N_NODES + 255) / 256, 256>>>();
    hist_kernel<<<(N_EDGES + 255) / 256, 256>>>(dst);
    scan_kernel<<<1, 1024>>>();
    fill_kernel<<<(N_EDGES + 255) / 256, 256>>>(src, dst);

    // input embedding: h = x @ W_in^T + b_in  (B[k][n] = W_in[n*128+k])
    {
        dim3 grid((N_NODES + 63) / 64, (D + 63) / 64);
        sgemm_kernel<<<grid, 256>>>(x, W_in, hptr, b_in, N_NODES, D, 1, D);
    }

    for (int l = 0; l < L; l++) {
        // hp = h @ W_l[l]  (B[k][n] = W[k*512+n])
        dim3 grid((N_NODES + 63) / 64, (HD + 63) / 64);
        sgemm_kernel<<<grid, 256>>>(hptr, W_l + (long)l * D * HD, hpptr, nullptr,
                                    N_NODES, HD, HD, 1);
        scal_kernel<<<N_NODES, 128>>>(a_src + l * HD / 4 * 4 /* l*H*D */, a_dst + l * H * D);
        agg_kernel<<<N_NODES, 128>>>(b_l + l * D, l);
    }

    colmean_kernel<<<(N_NODES + 255) / 256, LD>>>();
    row0_kernel<<<1, 128>>>(W_xa, b_xa, W_r1, b_r1, W_r2, b_r2, out);
    readout_kernel<<<(N_EDGES + 3) / 4, 128>>>(state, W_r1, b_r1, W_r2, b_r2, out);
}

// round 2
// speedup vs baseline: 1.1718x; 1.1718x over previous
#include <cuda_runtime.h>
#include <cuda_bf16.h>

#define N_NODES 20000
#define N_EDGES 500000
#define BATCH   2
#define D       128
#define H       4
#define L       3
#define HD      (H*D)        // 512
#define LD      (L*D)        // 384
#define F       (L*H + 1)    // 13
#define LH      (L*H)        // 12
#define SLOPE   0.2f

// ---------------- scratch (static device globals; no allocation) ----------------
__device__ float g_h[N_NODES * D];
__device__ float g_hp[N_NODES * HD];
__device__ float g_as[N_NODES * H];
__device__ float g_ad[N_NODES * H];
__device__ float g_xacc[N_NODES * LD];
__device__ float g_ac[N_EDGES * LH];        // UNNORMALIZED exp(e) per edge
__device__ float g_inv[N_NODES * LH];       // 1/denominator per (node, layer, head)
__device__ int   g_deg[N_NODES];
__device__ int   g_rowptr[N_NODES + 1];
__device__ int   g_cursor[N_NODES];
__device__ int   g_csr_src[N_EDGES];
__device__ int   g_csr_eid[N_EDGES];
__device__ float g_colsum[LD];

// ---------------- init / CSR build ----------------
__global__ void zero_kernel() {
    int i = blockIdx.x * blockDim.x + threadIdx.x;
    if (i < N_NODES) g_deg[i] = 0;
    if (i < LD)      g_colsum[i] = 0.f;
}

__global__ void hist_kernel(const int* __restrict__ dst) {
    int e = blockIdx.x * blockDim.x + threadIdx.x;
    if (e < N_EDGES) atomicAdd(&g_deg[dst[e]], 1);
}

__global__ void __launch_bounds__(1024) scan_kernel() {
    __shared__ int sh[1024];
    const int t = threadIdx.x;
    const int C = (N_NODES + 1023) / 1024;
    int start = t * C, end = min(start + C, N_NODES);
    int s = 0;
    for (int i = start; i < end; i++) s += g_deg[i];
    sh[t] = s;
    __syncthreads();
    for (int off = 1; off < 1024; off <<= 1) {
        int v = (t >= off) ? sh[t - off] : 0;
        __syncthreads();
        sh[t] += v;
        __syncthreads();
    }
    int run = sh[t] - s;
    for (int i = start; i < end; i++) {
        g_rowptr[i] = run;
        g_cursor[i] = run;
        run += g_deg[i];
    }
    if (t == 1023) g_rowptr[N_NODES] = sh[1023];
}

__global__ void fill_kernel(const int* __restrict__ src, const int* __restrict__ dst) {
    int e = blockIdx.x * blockDim.x + threadIdx.x;
    if (e < N_EDGES) {
        int d = dst[e];
        int pos = atomicAdd(&g_cursor[d], 1);
        g_csr_src[pos] = src[e];
        g_csr_eid[pos] = e;
    }
}

// ---------------- tf32 tensor-core GEMM ----------------
// C[M,N] = A[M,128] @ B, where B[k][n] = Bp[k*ldbk + n*ldbn]. K fixed at 128.
// Block tile 128x64, BK=32, 256 threads (8 warps, 4x2), warp tile 32x32.
__device__ __forceinline__ unsigned f2tf32(float x) {
    unsigned u;
    asm("cvt.rna.tf32.f32 %0, %1;" : "=r"(u) : "f"(x));
    return u;
}

__global__ void __launch_bounds__(256) tf32_gemm_kernel(
    const float* __restrict__ A, const float* __restrict__ B,
    float* __restrict__ C, const float* __restrict__ bias,
    int M, int N, int ldbk, int ldbn)
{
    __shared__ float As[128][36];  // [row][k], stride 36 -> conflict-free frag reads
    __shared__ float Bs[64][36];   // [n][k] transposed, stride 36

    const int tid = threadIdx.x;
    const int bm = blockIdx.x * 128, bn = blockIdx.y * 64;
    const int wid = tid >> 5, lane = tid & 31;
    const int wm = (wid >> 1) * 32, wn = (wid & 1) * 32;
    const int g = lane >> 2, tig = lane & 3;

    float c[2][4][4];
    #pragma unroll
    for (int mi = 0; mi < 2; mi++)
        #pragma unroll
        for (int ni = 0; ni < 4; ni++)
            #pragma unroll
            for (int r = 0; r < 4; r++) c[mi][ni][r] = 0.f;

    for (int k0 = 0; k0 < 128; k0 += 32) {
        // load A tile: 128 rows x 32 k, float4 per thread x4
        #pragma unroll
        for (int s = 0; s < 4; s++) {
            int i = tid + s * 256;
            int row = i >> 3, kc = (i & 7) * 4;
            float4 av = make_float4(0.f, 0.f, 0.f, 0.f);
            if (bm + row < M) av = *(const float4*)(A + (long)(bm + row) * 128 + k0 + kc);
            As[row][kc + 0] = __uint_as_float(f2tf32(av.x));
            As[row][kc + 1] = __uint_as_float(f2tf32(av.y));
            As[row][kc + 2] = __uint_as_float(f2tf32(av.z));
            As[row][kc + 3] = __uint_as_float(f2tf32(av.w));
        }
        // load B tile (transposed into [n][k])
        if (ldbn == 1) {
            // B row-major [k][n]: coalesce along n
            #pragma unroll
            for (int s = 0; s < 8; s++) {
                int i = tid + s * 256;
                int kk = i >> 6, nn = i & 63;
                float v = (bn + nn < N) ? B[(long)(k0 + kk) * ldbk + bn + nn] : 0.f;
                Bs[nn][kk] = __uint_as_float(f2tf32(v));
            }
        } else {
            // B with k contiguous (ldbk==1): coalesce along k
            #pragma unroll
            for (int s = 0; s < 8; s++) {
                int i = tid + s * 256;
                int kk = i & 31, nn = i >> 5;
                float v = (bn + nn < N) ? B[(k0 + kk) + (long)(bn + nn) * ldbn] : 0.f;
                Bs[nn][kk] = __uint_as_float(f2tf32(v));
            }
        }
        __syncthreads();

        #pragma unroll
        for (int ks = 0; ks < 4; ks++) {
            const int kb = ks * 8;
            unsigned a[2][4];
            #pragma unroll
            for (int mi = 0; mi < 2; mi++) {
                int r = wm + mi * 16;
                a[mi][0] = __float_as_uint(As[r + g][kb + tig]);
                a[mi][1] = __float_as_uint(As[r + g + 8][kb + tig]);
                a[mi][2] = __float_as_uint(As[r + g][kb + tig + 4]);
                a[mi][3] = __float_as_uint(As[r + g + 8][kb + tig + 4]);
            }
            #pragma unroll
            for (int ni = 0; ni < 4; ni++) {
                unsigned b0 = __float_as_uint(Bs[wn + ni * 8 + g][kb + tig]);
                unsigned b1 = __float_as_uint(Bs[wn + ni * 8 + g][kb + tig + 4]);
                #pragma unroll
                for (int mi = 0; mi < 2; mi++) {
                    asm volatile(
                        "mma.sync.aligned.m16n8k8.row.col.f32.tf32.tf32.f32 "
                        "{%0,%1,%2,%3}, {%4,%5,%6,%7}, {%8,%9}, {%0,%1,%2,%3};"
                        : "+f"(c[mi][ni][0]), "+f"(c[mi][ni][1]),
                          "+f"(c[mi][ni][2]), "+f"(c[mi][ni][3])
                        : "r"(a[mi][0]), "r"(a[mi][1]), "r"(a[mi][2]), "r"(a[mi][3]),
                          "r"(b0), "r"(b1));
                }
            }
        }
        __syncthreads();
    }

    // epilogue
    #pragma unroll
    for (int mi = 0; mi < 2; mi++) {
        int row0 = bm + wm + mi * 16 + g;
        int row1 = row0 + 8;
        #pragma unroll
        for (int ni = 0; ni < 4; ni++) {
            int col = bn + wn + ni * 8 + 2 * tig;
            float bx = 0.f, by = 0.f;
            if (bias) { bx = bias[col]; by = bias[col + 1]; }
            if (row0 < M) {
                float2 v = make_float2(c[mi][ni][0] + bx, c[mi][ni][1] + by);
                *(float2*)(C + (long)row0 * N + col) = v;
            }
            if (row1 < M) {
                float2 v = make_float2(c[mi][ni][2] + bx, c[mi][ni][3] + by);
                *(float2*)(C + (long)row1 * N + col) = v;
            }
        }
    }
}

// ---------------- per-(node,head) attention scalars ----------------
__global__ void __launch_bounds__(128) scal_kernel(
    const float* __restrict__ a_s, const float* __restrict__ a_d)
{
    int n = blockIdx.x;
    int w = threadIdx.x >> 5, ln = threadIdx.x & 31;
    const float* hpn = g_hp + n * HD + w * D;
    float ss = 0.f, sd = 0.f;
    #pragma unroll
    for (int j = 0; j < 4; j++) {
        int c = ln + 32 * j;
        float v = hpn[c];
        ss += v * a_s[w * D + c];
        sd += v * a_d[w * D + c];
    }
    #pragma unroll
    for (int off = 16; off; off >>= 1) {
        ss += __shfl_xor_sync(0xffffffffu, ss, off);
        sd += __shfl_xor_sync(0xffffffffu, sd, off);
    }
    if (ln == 0) {
        g_as[n * H + w] = ss;
        g_ad[n * H + w] = sd;
    }
}

// ---------------- single-pass softmax-aggregation (deferred normalization) ----------------
__global__ void __launch_bounds__(128) agg_kernel(const float* __restrict__ b_l, int layer) {
    __shared__ float sh[HD];
    const int n = blockIdx.x;
    const int w = threadIdx.x >> 5, ln = threadIdx.x & 31;
    const int start = g_rowptr[n], end = g_rowptr[n + 1];
    const float ad_h = g_ad[n * H + w];

    float sum_ex = 0.f;
    float4 acc = make_float4(0.f, 0.f, 0.f, 0.f);
    #pragma unroll 2
    for (int i = start; i < end; i++) {
        int src = g_csr_src[i];
        float ev = g_as[src * H + w] + ad_h;
        ev = ev > 0.f ? ev : SLOPE * ev;
        float ex = __expf(ev);
        sum_ex += ex;
        float4 v = *(const float4*)(g_hp + src * HD + w * D + ln * 4);
        acc.x += ex * v.x;
        acc.y += ex * v.y;
        acc.z += ex * v.z;
        acc.w += ex * v.w;
        if (ln == 0) g_ac[(long)g_csr_eid[i] * LH + layer * H + w] = ex;  // unnormalized
    }
    const float inv = 1.0f / (sum_ex + 1e-16f);
    acc.x *= inv; acc.y *= inv; acc.z *= inv; acc.w *= inv;
    if (ln == 0) g_inv[n * LH + layer * H + w] = inv;
    *(float4*)&sh[w * D + ln * 4] = acc;
    __syncthreads();

    int t = threadIdx.x;
    float v = 0.25f * (sh[t] + sh[D + t] + sh[2 * D + t] + sh[3 * D + t]) + b_l[t];
    g_xacc[n * LD + layer * D + t] = v;
    g_h[n * D + t] = v > 0.f ? v : SLOPE * v;
}

// ---------------- column means of xacc ----------------
__global__ void __launch_bounds__(LD) colmean_kernel() {
    int col = threadIdx.x;
    int n0 = blockIdx.x * 256, n1 = min(n0 + 256, N_NODES);
    float s = 0.f;
    for (int n = n0; n < n1; n++) s += g_xacc[n * LD + col];
    atomicAdd(&g_colsum[col], s);
}

// ---------------- row 0 of output ----------------
__global__ void __launch_bounds__(128) row0_kernel(
    const float* __restrict__ W_xa, const float* __restrict__ b_xa,
    const float* __restrict__ W_r1, const float* __restrict__ b_r1,
    const float* __restrict__ W_r2, const float* __restrict__ b_r2,
    float* __restrict__ out)
{
    __shared__ float smean[LD];
    __shared__ float sxl[F];
    __shared__ float red[128];
    int t = threadIdx.x;
    for (int i = t; i < LD; i += 128) smean[i] = g_colsum[i] * (1.0f / N_NODES);
    __syncthreads();
    if (t < F) {
        float s = b_xa[t];
        for (int k = 0; k < LD; k++) s += smean[k] * W_xa[t * LD + k];
        sxl[t] = s;
    }
    __syncthreads();
    float hsum = b_r1[t];
    #pragma unroll
    for (int j = 0; j < F; j++) hsum += sxl[j] * W_r1[t * F + j];
    hsum = fmaxf(hsum, 0.f);
    red[t] = W_r2[t] * hsum;
    __syncthreads();
    for (int off = 64; off; off >>= 1) {
        if (t < off) red[t] += red[t + off];
        __syncthreads();
    }
    if (t == 0) {
        float v = red[0] + b_r2[0];
        out[0] = v;
        out[N_EDGES + 1] = v;
    }
}

// ---------------- per-edge readout (normalizes alpha on the fly) ----------------
__global__ void __launch_bounds__(128) readout_kernel(
    const float* __restrict__ state, const int* __restrict__ dst,
    const float* __restrict__ W_r1, const float* __restrict__ b_r1,
    const float* __restrict__ W_r2, const float* __restrict__ b_r2,
    float* __restrict__ out)
{
    __shared__ float sW1t[F * 128];
    __shared__ float sb1[128];
    __shared__ float sW2[128];
    int t = threadIdx.x;
    #pragma unroll
    for (int j = 0; j < F; j++) sW1t[j * 128 + t] = W_r1[t * F + j];
    sb1[t] = b_r1[t];
    sW2[t] = W_r2[t];
    __syncthreads();
    float br2 = b_r2[0];

    int w = t >> 5, ln = t & 31;
    int e = blockIdx.x * 4 + w;
    if (e >= N_EDGES) return;
    int c = ln * 4;

    int de = dst[e];
    const float* inve = g_inv + de * LH;
    const float* ace = g_ac + (long)e * LH;

    float u0 = sb1[c], u1 = sb1[c + 1], u2 = sb1[c + 2], u3 = sb1[c + 3];
    #pragma unroll
    for (int j = 0; j < LH; j++) {
        float a = ace[j] * inve[j];
        const float* wr = &sW1t[(j + 1) * 128 + c];
        u0 += a * wr[0]; u1 += a * wr[1]; u2 += a * wr[2]; u3 += a * wr[3];
    }
    float v0 = sW1t[c], v1 = sW1t[c + 1], v2 = sW1t[c + 2], v3 = sW1t[c + 3];
    float q0 = sW2[c], q1 = sW2[c + 1], q2 = sW2[c + 2], q3 = sW2[c + 3];

    #pragma unroll
    for (int b = 0; b < BATCH; b++) {
        float s = state[(long)b * N_EDGES + e];
        float p = q0 * fmaxf(u0 + s * v0, 0.f)
                + q1 * fmaxf(u1 + s * v1, 0.f)
                + q2 * fmaxf(u2 + s * v2, 0.f)
                + q3 * fmaxf(u3 + s * v3, 0.f);
        #pragma unroll
        for (int off = 16; off; off >>= 1) p += __shfl_xor_sync(0xffffffffu, p, off);
        if (ln == 0) out[(long)b * (N_EDGES + 1) + 1 + e] = p + br2;
    }
}

// ---------------- launch ----------------
extern "C" void kernel_launch(void* const* d_in, const int* in_sizes, int n_in,
                              void* d_out, int out_size)
{
    const float* state = (const float*)d_in[0];
    const int*   ei    = (const int*)d_in[1];
    const float* x     = (const float*)d_in[2];
    const float* W_in  = (const float*)d_in[3];
    const float* b_in  = (const float*)d_in[4];
    const float* W_l   = (const float*)d_in[5];
    const float* a_src = (const float*)d_in[6];
    const float* a_dst = (const float*)d_in[7];
    const float* b_l   = (const float*)d_in[8];
    const float* W_xa  = (const float*)d_in[9];
    const float* b_xa  = (const float*)d_in[10];
    const float* W_r1  = (const float*)d_in[11];
    const float* b_r1  = (const float*)d_in[12];
    const float* W_r2  = (const float*)d_in[13];
    const float* b_r2  = (const float*)d_in[14];
    float* out = (float*)d_out;

    const int* src = ei;
    const int* dst = ei + N_EDGES;

    float* hptr;  cudaGetSymbolAddress((void**)&hptr,  g_h);
    float* hpptr; cudaGetSymbolAddress((void**)&hpptr, g_hp);

    zero_kernel<<<(N_NODES + 255) / 256, 256>>>();
    hist_kernel<<<(N_EDGES + 255) / 256, 256>>>(dst);
    scan_kernel<<<1, 1024>>>();
    fill_kernel<<<(N_EDGES + 255) / 256, 256>>>(src, dst);

    // input embedding: h = x @ W_in^T + b_in  (B[k][n] = W_in[n*128+k])
    {
        dim3 grid((N_NODES + 127) / 128, D / 64);
        tf32_gemm_kernel<<<grid, 256>>>(x, W_in, hptr, b_in, N_NODES, D, 1, D);
    }

    for (int l = 0; l < L; l++) {
        dim3 grid((N_NODES + 127) / 128, HD / 64);
        tf32_gemm_kernel<<<grid, 256>>>(hptr, W_l + (long)l * D * HD, hpptr, nullptr,
                                        N_NODES, HD, HD, 1);
        scal_kernel<<<N_NODES, 128>>>(a_src + l * H * D, a_dst + l * H * D);
        agg_kernel<<<N_NODES, 128>>>(b_l + l * D, l);
    }

    colmean_kernel<<<(N_NODES + 255) / 256, LD>>>();
    row0_kernel<<<1, 128>>>(W_xa, b_xa, W_r1, b_r1, W_r2, b_r2, out);
    readout_kernel<<<(N_EDGES + 3) / 4, 128>>>(state, dst, W_r1, b_r1, W_r2, b_r2, out);
}

// round 4
// speedup vs baseline: 1.2266x; 1.0468x over previous
#include <cuda_runtime.h>
#include <cuda_bf16.h>

#define N_NODES 20000
#define N_EDGES 500000
#define BATCH   2
#define D       128
#define H       4
#define L       3
#define HD      (H*D)        // 512
#define LD      (L*D)        // 384
#define F       (L*H + 1)    // 13
#define LH      (L*H)        // 12
#define SLOPE   0.2f

// ---------------- scratch ----------------
__device__ float          g_h[N_NODES * D];      // fp32 node features (GEMM A operand)
__device__ __nv_bfloat16  g_hpb[N_NODES * HD];   // bf16 projected features (gather source)
__device__ float g_as[N_NODES * H];              // alpha_src scalars (atomic-accumulated)
__device__ float g_ad[N_NODES * H];
__device__ float g_xacc[N_NODES * LD];
__device__ float g_ac[N_EDGES * LH];             // unnormalized exp(e)
__device__ float g_inv[N_NODES * LH];            // 1/denominator
__device__ int   g_deg[N_NODES];
__device__ int   g_rowptr[N_NODES + 1];
__device__ int   g_cursor[N_NODES];
__device__ int   g_csr_src[N_EDGES];
__device__ int   g_csr_eid[N_EDGES];
__device__ float g_colsum[LD];

// ---------------- init / CSR build ----------------
__global__ void zero_kernel() {
    int i = blockIdx.x * blockDim.x + threadIdx.x;
    if (i < N_NODES) g_deg[i] = 0;
    if (i < N_NODES * H) { g_as[i] = 0.f; g_ad[i] = 0.f; }
    if (i < LD) g_colsum[i] = 0.f;
}

// zero only the alpha accumulators (between layers; must NOT be fused into agg)
__global__ void zero_as_kernel() {
    int i = blockIdx.x * blockDim.x + threadIdx.x;
    if (i < N_NODES * H) { g_as[i] = 0.f; g_ad[i] = 0.f; }
}

__global__ void hist_kernel(const int* __restrict__ dst) {
    int e = blockIdx.x * blockDim.x + threadIdx.x;
    if (e < N_EDGES) atomicAdd(&g_deg[dst[e]], 1);
}

__global__ void __launch_bounds__(1024) scan_kernel() {
    __shared__ int sh[1024];
    const int t = threadIdx.x;
    const int C = (N_NODES + 1023) / 1024;
    int start = t * C, end = min(start + C, N_NODES);
    int s = 0;
    for (int i = start; i < end; i++) s += g_deg[i];
    sh[t] = s;
    __syncthreads();
    for (int off = 1; off < 1024; off <<= 1) {
        int v = (t >= off) ? sh[t - off] : 0;
        __syncthreads();
        sh[t] += v;
        __syncthreads();
    }
    int run = sh[t] - s;
    for (int i = start; i < end; i++) {
        g_rowptr[i] = run;
        g_cursor[i] = run;
        run += g_deg[i];
    }
    if (t == 1023) g_rowptr[N_NODES] = sh[1023];
}

__global__ void fill_kernel(const int* __restrict__ src, const int* __restrict__ dst) {
    int e = blockIdx.x * blockDim.x + threadIdx.x;
    if (e < N_EDGES) {
        int d = dst[e];
        int pos = atomicAdd(&g_cursor[d], 1);
        g_csr_src[pos] = src[e];
        g_csr_eid[pos] = e;
    }
}

// ---------------- tf32 tensor-core GEMM (+ fused alpha epilogue) ----------------
__device__ __forceinline__ unsigned f2tf32(float x) {
    unsigned u;
    asm("cvt.rna.tf32.f32 %0, %1;" : "=r"(u) : "f"(x));
    return u;
}

__global__ void __launch_bounds__(256) tf32_gemm_kernel(
    const float* __restrict__ A, const float* __restrict__ B,
    float* __restrict__ Cf, const float* __restrict__ bias,
    __nv_bfloat16* __restrict__ hpb,
    const float* __restrict__ a_s, const float* __restrict__ a_d,
    float* __restrict__ as_out, float* __restrict__ ad_out,
    int M, int N, int ldbk, int ldbn)
{
    __shared__ float As[128][36];
    __shared__ float Bs[64][36];

    const int tid = threadIdx.x;
    const int bm = blockIdx.x * 128, bn = blockIdx.y * 64;
    const int wid = tid >> 5, lane = tid & 31;
    const int wm = (wid >> 1) * 32, wn = (wid & 1) * 32;
    const int g = lane >> 2, tig = lane & 3;

    float c[2][4][4];
    #pragma unroll
    for (int mi = 0; mi < 2; mi++)
        #pragma unroll
        for (int ni = 0; ni < 4; ni++)
            #pragma unroll
            for (int r = 0; r < 4; r++) c[mi][ni][r] = 0.f;

    for (int k0 = 0; k0 < 128; k0 += 32) {
        #pragma unroll
        for (int s = 0; s < 4; s++) {
            int i = tid + s * 256;
            int row = i >> 3, kc = (i & 7) * 4;
            float4 av = make_float4(0.f, 0.f, 0.f, 0.f);
            if (bm + row < M) av = *(const float4*)(A + (long)(bm + row) * 128 + k0 + kc);
            As[row][kc + 0] = __uint_as_float(f2tf32(av.x));
            As[row][kc + 1] = __uint_as_float(f2tf32(av.y));
            As[row][kc + 2] = __uint_as_float(f2tf32(av.z));
            As[row][kc + 3] = __uint_as_float(f2tf32(av.w));
        }
        if (ldbn == 1) {
            #pragma unroll
            for (int s = 0; s < 8; s++) {
                int i = tid + s * 256;
                int kk = i >> 6, nn = i & 63;
                float v = (bn + nn < N) ? B[(long)(k0 + kk) * ldbk + bn + nn] : 0.f;
                Bs[nn][kk] = __uint_as_float(f2tf32(v));
            }
        } else {
            #pragma unroll
            for (int s = 0; s < 8; s++) {
                int i = tid + s * 256;
                int kk = i & 31, nn = i >> 5;
                float v = (bn + nn < N) ? B[(k0 + kk) + (long)(bn + nn) * ldbn] : 0.f;
                Bs[nn][kk] = __uint_as_float(f2tf32(v));
            }
        }
        __syncthreads();

        #pragma unroll
        for (int ks = 0; ks < 4; ks++) {
            const int kb = ks * 8;
            unsigned a[2][4];
            #pragma unroll
            for (int mi = 0; mi < 2; mi++) {
                int r = wm + mi * 16;
                a[mi][0] = __float_as_uint(As[r + g][kb + tig]);
                a[mi][1] = __float_as_uint(As[r + g + 8][kb + tig]);
                a[mi][2] = __float_as_uint(As[r + g][kb + tig + 4]);
                a[mi][3] = __float_as_uint(As[r + g + 8][kb + tig + 4]);
            }
            #pragma unroll
            for (int ni = 0; ni < 4; ni++) {
                unsigned b0 = __float_as_uint(Bs[wn + ni * 8 + g][kb + tig]);
                unsigned b1 = __float_as_uint(Bs[wn + ni * 8 + g][kb + tig + 4]);
                #pragma unroll
                for (int mi = 0; mi < 2; mi++) {
                    asm volatile(
                        "mma.sync.aligned.m16n8k8.row.col.f32.tf32.tf32.f32 "
                        "{%0,%1,%2,%3}, {%4,%5,%6,%7}, {%8,%9}, {%0,%1,%2,%3};"
                        : "+f"(c[mi][ni][0]), "+f"(c[mi][ni][1]),
                          "+f"(c[mi][ni][2]), "+f"(c[mi][ni][3])
                        : "r"(a[mi][0]), "r"(a[mi][1]), "r"(a[mi][2]), "r"(a[mi][3]),
                          "r"(b0), "r"(b1));
                }
            }
        }
        __syncthreads();
    }

    if (Cf) {
        #pragma unroll
        for (int mi = 0; mi < 2; mi++) {
            int row0 = bm + wm + mi * 16 + g;
            int row1 = row0 + 8;
            #pragma unroll
            for (int ni = 0; ni < 4; ni++) {
                int col = bn + wn + ni * 8 + 2 * tig;
                float bx = bias ? bias[col] : 0.f;
                float by = bias ? bias[col + 1] : 0.f;
                if (row0 < M)
                    *(float2*)(Cf + (long)row0 * N + col) =
                        make_float2(c[mi][ni][0] + bx, c[mi][ni][1] + by);
                if (row1 < M)
                    *(float2*)(Cf + (long)row1 * N + col) =
                        make_float2(c[mi][ni][2] + bx, c[mi][ni][3] + by);
            }
        }
    }

    if (hpb) {
        const int head = bn >> 7;   // 64-col tile lies within one head
        #pragma unroll
        for (int mi = 0; mi < 2; mi++) {
            int row0 = bm + wm + mi * 16 + g;
            int row1 = row0 + 8;
            float sa0 = 0.f, sd0 = 0.f, sa1 = 0.f, sd1 = 0.f;
            #pragma unroll
            for (int ni = 0; ni < 4; ni++) {
                int col = bn + wn + ni * 8 + 2 * tig;
                float w0s = __ldg(a_s + col), w1s = __ldg(a_s + col + 1);
                float w0d = __ldg(a_d + col), w1d = __ldg(a_d + col + 1);
                sa0 += c[mi][ni][0] * w0s + c[mi][ni][1] * w1s;
                sd0 += c[mi][ni][0] * w0d + c[mi][ni][1] * w1d;
                sa1 += c[mi][ni][2] * w0s + c[mi][ni][3] * w1s;
                sd1 += c[mi][ni][2] * w0d + c[mi][ni][3] * w1d;
                __nv_bfloat162 h0 = __floats2bfloat162_rn(c[mi][ni][0], c[mi][ni][1]);
                __nv_bfloat162 h1 = __floats2bfloat162_rn(c[mi][ni][2], c[mi][ni][3]);
                if (row0 < M) *(__nv_bfloat162*)(hpb + (long)row0 * N + col) = h0;
                if (row1 < M) *(__nv_bfloat162*)(hpb + (long)row1 * N + col) = h1;
            }
            #pragma unroll
            for (int off = 1; off < 4; off <<= 1) {
                sa0 += __shfl_xor_sync(0xffffffffu, sa0, off);
                sd0 += __shfl_xor_sync(0xffffffffu, sd0, off);
                sa1 += __shfl_xor_sync(0xffffffffu, sa1, off);
                sd1 += __shfl_xor_sync(0xffffffffu, sd1, off);
            }
            if (tig == 0) {
                if (row0 < M) {
                    atomicAdd(&as_out[row0 * H + head], sa0);
                    atomicAdd(&ad_out[row0 * H + head], sd0);
                }
                if (row1 < M) {
                    atomicAdd(&as_out[row1 * H + head], sa1);
                    atomicAdd(&ad_out[row1 * H + head], sd1);
                }
            }
        }
    }
}

// ---------------- single-pass softmax-aggregation (bf16 gathers, deferred norm) ----------------
__global__ void __launch_bounds__(128) agg_kernel(const float* __restrict__ b_l, int layer) {
    __shared__ float sh[HD];
    const int n = blockIdx.x;
    const int w = threadIdx.x >> 5, ln = threadIdx.x & 31;
    const int start = g_rowptr[n], end = g_rowptr[n + 1];
    const float ad_h = g_ad[n * H + w];

    float sum_ex = 0.f;
    float4 acc = make_float4(0.f, 0.f, 0.f, 0.f);
    #pragma unroll 4
    for (int i = start; i < end; i++) {
        int src = g_csr_src[i];
        float ev = g_as[src * H + w] + ad_h;
        ev = ev > 0.f ? ev : SLOPE * ev;
        float ex = __expf(ev);
        sum_ex += ex;
        uint2 u = *(const uint2*)(g_hpb + (long)src * HD + w * D + ln * 4);
        float2 f0 = __bfloat1622float2(*reinterpret_cast<__nv_bfloat162*>(&u.x));
        float2 f1 = __bfloat1622float2(*reinterpret_cast<__nv_bfloat162*>(&u.y));
        acc.x += ex * f0.x;
        acc.y += ex * f0.y;
        acc.z += ex * f1.x;
        acc.w += ex * f1.y;
        if (ln == 0) g_ac[(long)g_csr_eid[i] * LH + layer * H + w] = ex;
    }
    const float inv = 1.0f / (sum_ex + 1e-16f);
    acc.x *= inv; acc.y *= inv; acc.z *= inv; acc.w *= inv;
    if (ln == 0) g_inv[n * LH + layer * H + w] = inv;
    *(float4*)&sh[w * D + ln * 4] = acc;
    __syncthreads();

    int t = threadIdx.x;
    float v = 0.25f * (sh[t] + sh[D + t] + sh[2 * D + t] + sh[3 * D + t]) + b_l[t];
    g_xacc[n * LD + layer * D + t] = v;
    g_h[n * D + t] = v > 0.f ? v : SLOPE * v;
    // NOTE: no zeroing of g_as/g_ad here — other blocks still read them (race!).
}

// ---------------- column means ----------------
__global__ void __launch_bounds__(LD) colmean_kernel() {
    int col = threadIdx.x;
    int n0 = blockIdx.x * 256, n1 = min(n0 + 256, N_NODES);
    float s = 0.f;
    for (int n = n0; n < n1; n++) s += g_xacc[n * LD + col];
    atomicAdd(&g_colsum[col], s);
}

// ---------------- row 0 of output ----------------
__global__ void __launch_bounds__(128) row0_kernel(
    const float* __restrict__ W_xa, const float* __restrict__ b_xa,
    const float* __restrict__ W_r1, const float* __restrict__ b_r1,
    const float* __restrict__ W_r2, const float* __restrict__ b_r2,
    float* __restrict__ out)
{
    __shared__ float smean[LD];
    __shared__ float sxl[F];
    __shared__ float red[128];
    int t = threadIdx.x;
    for (int i = t; i < LD; i += 128) smean[i] = g_colsum[i] * (1.0f / N_NODES);
    __syncthreads();
    if (t < F) {
        float s = b_xa[t];
        for (int k = 0; k < LD; k++) s += smean[k] * W_xa[t * LD + k];
        sxl[t] = s;
    }
    __syncthreads();
    float hsum = b_r1[t];
    #pragma unroll
    for (int j = 0; j < F; j++) hsum += sxl[j] * W_r1[t * F + j];
    hsum = fmaxf(hsum, 0.f);
    red[t] = W_r2[t] * hsum;
    __syncthreads();
    for (int off = 64; off; off >>= 1) {
        if (t < off) red[t] += red[t + off];
        __syncthreads();
    }
    if (t == 0) {
        float v = red[0] + b_r2[0];
        out[0] = v;
        out[N_EDGES + 1] = v;
    }
}

// ---------------- per-edge readout ----------------
__global__ void __launch_bounds__(128) readout_kernel(
    const float* __restrict__ state, const int* __restrict__ dst,
    const float* __restrict__ W_r1, const float* __restrict__ b_r1,
    const float* __restrict__ W_r2, const float* __restrict__ b_r2,
    float* __restrict__ out)
{
    __shared__ float sW1t[F * 128];
    __shared__ float sb1[128];
    __shared__ float sW2[128];
    int t = threadIdx.x;
    #pragma unroll
    for (int j = 0; j < F; j++) sW1t[j * 128 + t] = W_r1[t * F + j];
    sb1[t] = b_r1[t];
    sW2[t] = W_r2[t];
    __syncthreads();
    float br2 = b_r2[0];

    int w = t >> 5, ln = t & 31;
    int e = blockIdx.x * 4 + w;
    if (e >= N_EDGES) return;
    int c = ln * 4;

    int de = dst[e];
    const float* inve = g_inv + de * LH;
    const float* ace = g_ac + (long)e * LH;

    float u0 = sb1[c], u1 = sb1[c + 1], u2 = sb1[c + 2], u3 = sb1[c + 3];
    #pragma unroll
    for (int j = 0; j < LH; j++) {
        float a = ace[j] * inve[j];
        const float* wr = &sW1t[(j + 1) * 128 + c];
        u0 += a * wr[0]; u1 += a * wr[1]; u2 += a * wr[2]; u3 += a * wr[3];
    }
    float v0 = sW1t[c], v1 = sW1t[c + 1], v2 = sW1t[c + 2], v3 = sW1t[c + 3];
    float q0 = sW2[c], q1 = sW2[c + 1], q2 = sW2[c + 2], q3 = sW2[c + 3];

    #pragma unroll
    for (int b = 0; b < BATCH; b++) {
        float s = state[(long)b * N_EDGES + e];
        float p = q0 * fmaxf(u0 + s * v0, 0.f)
                + q1 * fmaxf(u1 + s * v1, 0.f)
                + q2 * fmaxf(u2 + s * v2, 0.f)
                + q3 * fmaxf(u3 + s * v3, 0.f);
        #pragma unroll
        for (int off = 16; off; off >>= 1) p += __shfl_xor_sync(0xffffffffu, p, off);
        if (ln == 0) out[(long)b * (N_EDGES + 1) + 1 + e] = p + br2;
    }
}

// ---------------- launch ----------------
extern "C" void kernel_launch(void* const* d_in, const int* in_sizes, int n_in,
                              void* d_out, int out_size)
{
    const float* state = (const float*)d_in[0];
    const int*   ei    = (const int*)d_in[1];
    const float* x     = (const float*)d_in[2];
    const float* W_in  = (const float*)d_in[3];
    const float* b_in  = (const float*)d_in[4];
    const float* W_l   = (const float*)d_in[5];
    const float* a_src = (const float*)d_in[6];
    const float* a_dst = (const float*)d_in[7];
    const float* b_l   = (const float*)d_in[8];
    const float* W_xa  = (const float*)d_in[9];
    const float* b_xa  = (const float*)d_in[10];
    const float* W_r1  = (const float*)d_in[11];
    const float* b_r1  = (const float*)d_in[12];
    const float* W_r2  = (const float*)d_in[13];
    const float* b_r2  = (const float*)d_in[14];
    float* out = (float*)d_out;

    const int* src = ei;
    const int* dst = ei + N_EDGES;

    float* hptr;            cudaGetSymbolAddress((void**)&hptr,  g_h);
    __nv_bfloat16* hpbptr;  cudaGetSymbolAddress((void**)&hpbptr, g_hpb);
    float* asptr;           cudaGetSymbolAddress((void**)&asptr, g_as);
    float* adptr;           cudaGetSymbolAddress((void**)&adptr, g_ad);

    zero_kernel<<<(N_NODES * H + 255) / 256, 256>>>();
    hist_kernel<<<(N_EDGES + 255) / 256, 256>>>(dst);
    scan_kernel<<<1, 1024>>>();
    fill_kernel<<<(N_EDGES + 255) / 256, 256>>>(src, dst);

    // input embedding: h = x @ W_in^T + b_in
    {
        dim3 grid((N_NODES + 127) / 128, D / 64);
        tf32_gemm_kernel<<<grid, 256>>>(x, W_in, hptr, b_in,
                                        nullptr, nullptr, nullptr, nullptr, nullptr,
                                        N_NODES, D, 1, D);
    }

    for (int l = 0; l < L; l++) {
        if (l > 0) zero_as_kernel<<<(N_NODES * H + 255) / 256, 256>>>();
        dim3 grid((N_NODES + 127) / 128, HD / 64);
        tf32_gemm_kernel<<<grid, 256>>>(hptr, W_l + (long)l * D * HD,
                                        nullptr, nullptr, hpbptr,
                                        a_src + l * H * D, a_dst + l * H * D,
                                        asptr, adptr,
                                        N_NODES, HD, HD, 1);
        agg_kernel<<<N_NODES, 128>>>(b_l + l * D, l);
    }

    colmean_kernel<<<(N_NODES + 255) / 256, LD>>>();
    row0_kernel<<<1, 128>>>(W_xa, b_xa, W_r1, b_r1, W_r2, b_r2, out);
    readout_kernel<<<(N_EDGES + 3) / 4, 128>>>(state, dst, W_r1, b_r1, W_r2, b_r2, out);
}

// round 5
// speedup vs baseline: 1.3720x; 1.1185x over previous
#include <cuda_runtime.h>
#include <cuda_bf16.h>

#define N_NODES 20000
#define N_EDGES 500000
#define BATCH   2
#define D       128
#define H       4
#define L       3
#define HD      (H*D)        // 512
#define LD      (L*D)        // 384
#define F       (L*H + 1)    // 13
#define LH      (L*H)        // 12
#define SLOPE   0.2f

// ---------------- scratch ----------------
__device__ float          g_h[N_NODES * D];
__device__ __nv_bfloat16  g_hpb[N_NODES * HD];
__device__ float g_as[N_NODES * H];
__device__ float g_ad[N_NODES * H];
__device__ float g_xacc[N_NODES * LD];
__device__ float g_ac[N_EDGES * LH];
__device__ float g_inv[N_NODES * LH];
__device__ float g_WinT[D * D];                  // W_in transposed to [k][n]
__device__ int   g_deg[N_NODES];
__device__ int   g_rowptr[N_NODES + 1];
__device__ int   g_cursor[N_NODES];
__device__ int   g_csr_src[N_EDGES];
__device__ int   g_csr_eid[N_EDGES];
__device__ float g_colsum[LD];

// ---------------- init / CSR build ----------------
__global__ void zero_kernel() {
    int i = blockIdx.x * blockDim.x + threadIdx.x;
    if (i < N_NODES) g_deg[i] = 0;
    if (i < N_NODES * H) { g_as[i] = 0.f; g_ad[i] = 0.f; }
    if (i < LD) g_colsum[i] = 0.f;
}

__global__ void zero_as_kernel() {
    int i = blockIdx.x * blockDim.x + threadIdx.x;
    if (i < N_NODES * H) { g_as[i] = 0.f; g_ad[i] = 0.f; }
}

__global__ void hist_kernel(const int* __restrict__ dst) {
    int e = blockIdx.x * blockDim.x + threadIdx.x;
    if (e < N_EDGES) atomicAdd(&g_deg[dst[e]], 1);
}

__global__ void __launch_bounds__(1024) scan_kernel() {
    __shared__ int sh[1024];
    const int t = threadIdx.x;
    const int C = (N_NODES + 1023) / 1024;
    int start = t * C, end = min(start + C, N_NODES);
    int s = 0;
    for (int i = start; i < end; i++) s += g_deg[i];
    sh[t] = s;
    __syncthreads();
    for (int off = 1; off < 1024; off <<= 1) {
        int v = (t >= off) ? sh[t - off] : 0;
        __syncthreads();
        sh[t] += v;
        __syncthreads();
    }
    int run = sh[t] - s;
    for (int i = start; i < end; i++) {
        g_rowptr[i] = run;
        g_cursor[i] = run;
        run += g_deg[i];
    }
    if (t == 1023) g_rowptr[N_NODES] = sh[1023];
}

__global__ void fill_kernel(const int* __restrict__ src, const int* __restrict__ dst) {
    int e = blockIdx.x * blockDim.x + threadIdx.x;
    if (e < N_EDGES) {
        int d = dst[e];
        int pos = atomicAdd(&g_cursor[d], 1);
        g_csr_src[pos] = src[e];
        g_csr_eid[pos] = e;
    }
}

__global__ void transpose_win_kernel(const float* __restrict__ W_in) {
    int i = blockIdx.x * blockDim.x + threadIdx.x;
    if (i < D * D) {
        int n = i >> 7, k = i & 127;
        g_WinT[k * D + n] = W_in[n * D + k];
    }
}

// ---------------- tf32 tensor-core GEMM with cp.async pipeline ----------------
// C[M,N] = A[M,128] @ B[128,N]; B row-major [k][n] with row stride N.
// Block 128x64, BK=16, 2-stage cp.async double buffer, 8 warps (4x2), warp 32x32.
__global__ void __launch_bounds__(256) tf32_gemm_kernel(
    const float* __restrict__ A, const float* __restrict__ B,
    float* __restrict__ Cf, const float* __restrict__ bias,
    __nv_bfloat16* __restrict__ hpb,
    const float* __restrict__ a_s, const float* __restrict__ a_d,
    float* __restrict__ as_out, float* __restrict__ ad_out,
    int M, int N)
{
    __shared__ float As[2][128][20];   // [row][k], bank-bijective (20g+tig)
    __shared__ float Bs[2][16][68];    // [k][n],   bank-bijective (4tig+g)

    const int tid = threadIdx.x;
    const int bm = blockIdx.x * 128, bn = blockIdx.y * 64;
    const int wid = tid >> 5, lane = tid & 31;
    const int wm = (wid >> 1) * 32, wn = (wid & 1) * 32;
    const int g = lane >> 2, tig = lane & 3;

    unsigned As_base = (unsigned)__cvta_generic_to_shared(&As[0][0][0]);
    unsigned Bs_base = (unsigned)__cvta_generic_to_shared(&Bs[0][0][0]);

    // copy-thread coordinates
    const int a_row0 = tid >> 2, a_kc = (tid & 3) * 4;   // chunk tid -> rows 0..63
    const int b_row  = tid >> 4, b_nc = (tid & 15) * 4;

    float c[2][4][4];
    #pragma unroll
    for (int mi = 0; mi < 2; mi++)
        #pragma unroll
        for (int ni = 0; ni < 4; ni++)
            #pragma unroll
            for (int r = 0; r < 4; r++) c[mi][ni][r] = 0.f;

    auto prefetch = [&](int kt, int buf) {
        #pragma unroll
        for (int s = 0; s < 2; s++) {
            int row = a_row0 + s * 64;
            const float* srcp = A + (long)(bm + row) * 128 + kt * 16 + a_kc;
            unsigned dst = As_base + (unsigned)(((buf * 128 + row) * 20 + a_kc) * 4);
            int sz = (bm + row < M) ? 16 : 0;
            asm volatile("cp.async.cg.shared.global [%0], [%1], 16, %2;"
                         :: "r"(dst), "l"(srcp), "r"(sz));
        }
        {
            const float* srcp = B + (long)(kt * 16 + b_row) * N + bn + b_nc;
            unsigned dst = Bs_base + (unsigned)(((buf * 16 + b_row) * 68 + b_nc) * 4);
            asm volatile("cp.async.cg.shared.global [%0], [%1], 16, %2;"
                         :: "r"(dst), "l"(srcp), "r"(16));
        }
        asm volatile("cp.async.commit_group;");
    };

    prefetch(0, 0);

    #pragma unroll
    for (int kt = 0; kt < 8; kt++) {
        const int buf = kt & 1;
        if (kt < 7) {
            prefetch(kt + 1, (kt + 1) & 1);
            asm volatile("cp.async.wait_group 1;");
        } else {
            asm volatile("cp.async.wait_group 0;");
        }
        __syncthreads();

        #pragma unroll
        for (int ks = 0; ks < 2; ks++) {
            const int kb = ks * 8;
            unsigned a[2][4];
            #pragma unroll
            for (int mi = 0; mi < 2; mi++) {
                int r = wm + mi * 16;
                a[mi][0] = __float_as_uint(As[buf][r + g][kb + tig]);
                a[mi][1] = __float_as_uint(As[buf][r + g + 8][kb + tig]);
                a[mi][2] = __float_as_uint(As[buf][r + g][kb + tig + 4]);
                a[mi][3] = __float_as_uint(As[buf][r + g + 8][kb + tig + 4]);
            }
            #pragma unroll
            for (int ni = 0; ni < 4; ni++) {
                unsigned b0 = __float_as_uint(Bs[buf][kb + tig][wn + ni * 8 + g]);
                unsigned b1 = __float_as_uint(Bs[buf][kb + tig + 4][wn + ni * 8 + g]);
                #pragma unroll
                for (int mi = 0; mi < 2; mi++) {
                    asm volatile(
                        "mma.sync.aligned.m16n8k8.row.col.f32.tf32.tf32.f32 "
                        "{%0,%1,%2,%3}, {%4,%5,%6,%7}, {%8,%9}, {%0,%1,%2,%3};"
                        : "+f"(c[mi][ni][0]), "+f"(c[mi][ni][1]),
                          "+f"(c[mi][ni][2]), "+f"(c[mi][ni][3])
                        : "r"(a[mi][0]), "r"(a[mi][1]), "r"(a[mi][2]), "r"(a[mi][3]),
                          "r"(b0), "r"(b1));
                }
            }
        }
        __syncthreads();
    }

    if (Cf) {
        #pragma unroll
        for (int mi = 0; mi < 2; mi++) {
            int row0 = bm + wm + mi * 16 + g;
            int row1 = row0 + 8;
            #pragma unroll
            for (int ni = 0; ni < 4; ni++) {
                int col = bn + wn + ni * 8 + 2 * tig;
                float bx = bias ? bias[col] : 0.f;
                float by = bias ? bias[col + 1] : 0.f;
                if (row0 < M)
                    *(float2*)(Cf + (long)row0 * N + col) =
                        make_float2(c[mi][ni][0] + bx, c[mi][ni][1] + by);
                if (row1 < M)
                    *(float2*)(Cf + (long)row1 * N + col) =
                        make_float2(c[mi][ni][2] + bx, c[mi][ni][3] + by);
            }
        }
    }

    if (hpb) {
        const int head = bn >> 7;
        #pragma unroll
        for (int mi = 0; mi < 2; mi++) {
            int row0 = bm + wm + mi * 16 + g;
            int row1 = row0 + 8;
            float sa0 = 0.f, sd0 = 0.f, sa1 = 0.f, sd1 = 0.f;
            #pragma unroll
            for (int ni = 0; ni < 4; ni++) {
                int col = bn + wn + ni * 8 + 2 * tig;
                float w0s = __ldg(a_s + col), w1s = __ldg(a_s + col + 1);
                float w0d = __ldg(a_d + col), w1d = __ldg(a_d + col + 1);
                sa0 += c[mi][ni][0] * w0s + c[mi][ni][1] * w1s;
                sd0 += c[mi][ni][0] * w0d + c[mi][ni][1] * w1d;
                sa1 += c[mi][ni][2] * w0s + c[mi][ni][3] * w1s;
                sd1 += c[mi][ni][2] * w0d + c[mi][ni][3] * w1d;
                __nv_bfloat162 h0 = __floats2bfloat162_rn(c[mi][ni][0], c[mi][ni][1]);
                __nv_bfloat162 h1 = __floats2bfloat162_rn(c[mi][ni][2], c[mi][ni][3]);
                if (row0 < M) *(__nv_bfloat162*)(hpb + (long)row0 * N + col) = h0;
                if (row1 < M) *(__nv_bfloat162*)(hpb + (long)row1 * N + col) = h1;
            }
            #pragma unroll
            for (int off = 1; off < 4; off <<= 1) {
                sa0 += __shfl_xor_sync(0xffffffffu, sa0, off);
                sd0 += __shfl_xor_sync(0xffffffffu, sd0, off);
                sa1 += __shfl_xor_sync(0xffffffffu, sa1, off);
                sd1 += __shfl_xor_sync(0xffffffffu, sd1, off);
            }
            if (tig == 0) {
                if (row0 < M) {
                    atomicAdd(&as_out[row0 * H + head], sa0);
                    atomicAdd(&ad_out[row0 * H + head], sd0);
                }
                if (row1 < M) {
                    atomicAdd(&as_out[row1 * H + head], sa1);
                    atomicAdd(&ad_out[row1 * H + head], sd1);
                }
            }
        }
    }
}

// ---------------- single-pass softmax-aggregation (smem-prefetched CSR) ----------------
__global__ void __launch_bounds__(128) agg_kernel(const float* __restrict__ b_l, int layer) {
    __shared__ float sh[HD];
    __shared__ int s_src[128];
    __shared__ int s_eid[128];
    __shared__ float4 s_as[128];
    const int n = blockIdx.x;
    const int t = threadIdx.x;
    const int w = t >> 5, ln = t & 31;
    const int start = g_rowptr[n], end = g_rowptr[n + 1];
    const float ad_h = g_ad[n * H + w];

    float sum_ex = 0.f;
    float4 acc = make_float4(0.f, 0.f, 0.f, 0.f);

    for (int cs = start; cs < end; cs += 128) {
        int m = min(128, end - cs);
        __syncthreads();
        if (t < m) {
            int s = g_csr_src[cs + t];
            s_src[t] = s;
            s_eid[t] = g_csr_eid[cs + t];
            s_as[t] = *(const float4*)&g_as[s * H];
        }
        __syncthreads();
        #pragma unroll 4
        for (int i = 0; i < m; i++) {
            int src = s_src[i];
            float ev = ((const float*)&s_as[i])[w] + ad_h;
            ev = ev > 0.f ? ev : SLOPE * ev;
            float ex = __expf(ev);
            sum_ex += ex;
            uint2 u = *(const uint2*)(g_hpb + (long)src * HD + w * D + ln * 4);
            float2 f0 = __bfloat1622float2(*reinterpret_cast<__nv_bfloat162*>(&u.x));
            float2 f1 = __bfloat1622float2(*reinterpret_cast<__nv_bfloat162*>(&u.y));
            acc.x += ex * f0.x;
            acc.y += ex * f0.y;
            acc.z += ex * f1.x;
            acc.w += ex * f1.y;
            if (ln == 0) g_ac[(long)s_eid[i] * LH + layer * H + w] = ex;
        }
    }
    const float inv = 1.0f / (sum_ex + 1e-16f);
    acc.x *= inv; acc.y *= inv; acc.z *= inv; acc.w *= inv;
    if (ln == 0) g_inv[n * LH + layer * H + w] = inv;
    *(float4*)&sh[w * D + ln * 4] = acc;
    __syncthreads();

    float v = 0.25f * (sh[t] + sh[D + t] + sh[2 * D + t] + sh[3 * D + t]) + b_l[t];
    g_xacc[n * LD + layer * D + t] = v;
    g_h[n * D + t] = v > 0.f ? v : SLOPE * v;
}

// ---------------- column means ----------------
__global__ void __launch_bounds__(LD) colmean_kernel() {
    int col = threadIdx.x;
    int n0 = blockIdx.x * 256, n1 = min(n0 + 256, N_NODES);
    float s = 0.f;
    for (int n = n0; n < n1; n++) s += g_xacc[n * LD + col];
    atomicAdd(&g_colsum[col], s);
}

// ---------------- row 0 of output ----------------
__global__ void __launch_bounds__(128) row0_kernel(
    const float* __restrict__ W_xa, const float* __restrict__ b_xa,
    const float* __restrict__ W_r1, const float* __restrict__ b_r1,
    const float* __restrict__ W_r2, const float* __restrict__ b_r2,
    float* __restrict__ out)
{
    __shared__ float smean[LD];
    __shared__ float sxl[F];
    __shared__ float red[128];
    int t = threadIdx.x;
    for (int i = t; i < LD; i += 128) smean[i] = g_colsum[i] * (1.0f / N_NODES);
    __syncthreads();
    if (t < F) {
        float s = b_xa[t];
        for (int k = 0; k < LD; k++) s += smean[k] * W_xa[t * LD + k];
        sxl[t] = s;
    }
    __syncthreads();
    float hsum = b_r1[t];
    #pragma unroll
    for (int j = 0; j < F; j++) hsum += sxl[j] * W_r1[t * F + j];
    hsum = fmaxf(hsum, 0.f);
    red[t] = W_r2[t] * hsum;
    __syncthreads();
    for (int off = 64; off; off >>= 1) {
        if (t < off) red[t] += red[t + off];
        __syncthreads();
    }
    if (t == 0) {
        float v = red[0] + b_r2[0];
        out[0] = v;
        out[N_EDGES + 1] = v;
    }
}

// ---------------- per-edge readout (persistent blocks, warp-strided) ----------------
#define RO_BLOCKS 2048
__global__ void __launch_bounds__(128) readout_kernel(
    const float* __restrict__ state, const int* __restrict__ dst,
    const float* __restrict__ W_r1, const float* __restrict__ b_r1,
    const float* __restrict__ W_r2, const float* __restrict__ b_r2,
    float* __restrict__ out)
{
    __shared__ float sW1t[F * 128];
    __shared__ float sb1[128];
    __shared__ float sW2[128];
    int t = threadIdx.x;
    #pragma unroll
    for (int j = 0; j < F; j++) sW1t[j * 128 + t] = W_r1[t * F + j];
    sb1[t] = b_r1[t];
    sW2[t] = W_r2[t];
    __syncthreads();
    float br2 = b_r2[0];

    const int w = t >> 5, ln = t & 31;
    const int c = ln * 4;
    const float b10 = sb1[c], b11 = sb1[c + 1], b12 = sb1[c + 2], b13 = sb1[c + 3];
    const float v0 = sW1t[c], v1 = sW1t[c + 1], v2 = sW1t[c + 2], v3 = sW1t[c + 3];
    const float q0 = sW2[c], q1 = sW2[c + 1], q2 = sW2[c + 2], q3 = sW2[c + 3];

    const int nwarps = RO_BLOCKS * 4;
    for (int e = blockIdx.x * 4 + w; e < N_EDGES; e += nwarps) {
        int de = dst[e];
        const float* inve = g_inv + de * LH;
        const float* ace = g_ac + (long)e * LH;

        float u0 = b10, u1 = b11, u2 = b12, u3 = b13;
        #pragma unroll
        for (int j = 0; j < LH; j++) {
            float a = ace[j] * inve[j];
            const float* wr = &sW1t[(j + 1) * 128 + c];
            u0 += a * wr[0]; u1 += a * wr[1]; u2 += a * wr[2]; u3 += a * wr[3];
        }
        #pragma unroll
        for (int b = 0; b < BATCH; b++) {
            float s = state[(long)b * N_EDGES + e];
            float p = q0 * fmaxf(u0 + s * v0, 0.f)
                    + q1 * fmaxf(u1 + s * v1, 0.f)
                    + q2 * fmaxf(u2 + s * v2, 0.f)
                    + q3 * fmaxf(u3 + s * v3, 0.f);
            #pragma unroll
            for (int off = 16; off; off >>= 1) p += __shfl_xor_sync(0xffffffffu, p, off);
            if (ln == 0) out[(long)b * (N_EDGES + 1) + 1 + e] = p + br2;
        }
    }
}

// ---------------- launch ----------------
extern "C" void kernel_launch(void* const* d_in, const int* in_sizes, int n_in,
                              void* d_out, int out_size)
{
    const float* state = (const float*)d_in[0];
    const int*   ei    = (const int*)d_in[1];
    const float* x     = (const float*)d_in[2];
    const float* W_in  = (const float*)d_in[3];
    const float* b_in  = (const float*)d_in[4];
    const float* W_l   = (const float*)d_in[5];
    const float* a_src = (const float*)d_in[6];
    const float* a_dst = (const float*)d_in[7];
    const float* b_l   = (const float*)d_in[8];
    const float* W_xa  = (const float*)d_in[9];
    const float* b_xa  = (const float*)d_in[10];
    const float* W_r1  = (const float*)d_in[11];
    const float* b_r1  = (const float*)d_in[12];
    const float* W_r2  = (const float*)d_in[13];
    const float* b_r2  = (const float*)d_in[14];
    float* out = (float*)d_out;

    const int* src = ei;
    const int* dst = ei + N_EDGES;

    float* hptr;            cudaGetSymbolAddress((void**)&hptr,  g_h);
    __nv_bfloat16* hpbptr;  cudaGetSymbolAddress((void**)&hpbptr, g_hpb);
    float* asptr;           cudaGetSymbolAddress((void**)&asptr, g_as);
    float* adptr;           cudaGetSymbolAddress((void**)&adptr, g_ad);
    float* wintptr;         cudaGetSymbolAddress((void**)&wintptr, g_WinT);

    zero_kernel<<<(N_NODES * H + 255) / 256, 256>>>();
    hist_kernel<<<(N_EDGES + 255) / 256, 256>>>(dst);
    scan_kernel<<<1, 1024>>>();
    fill_kernel<<<(N_EDGES + 255) / 256, 256>>>(src, dst);
    transpose_win_kernel<<<(D * D + 255) / 256, 256>>>(W_in);

    // input embedding: h = x @ WinT (B row-major [k][n], N=128)
    {
        dim3 grid((N_NODES + 127) / 128, D / 64);
        tf32_gemm_kernel<<<grid, 256>>>(x, wintptr, hptr, b_in,
                                        nullptr, nullptr, nullptr, nullptr, nullptr,
                                        N_NODES, D);
    }

    for (int l = 0; l < L; l++) {
        if (l > 0) zero_as_kernel<<<(N_NODES * H + 255) / 256, 256>>>();
        dim3 grid((N_NODES + 127) / 128, HD / 64);
        tf32_gemm_kernel<<<grid, 256>>>(hptr, W_l + (long)l * D * HD,
                                        nullptr, nullptr, hpbptr,
                                        a_src + l * H * D, a_dst + l * H * D,
                                        asptr, adptr,
                                        N_NODES, HD);
        agg_kernel<<<N_NODES, 128>>>(b_l + l * D, l);
    }

    colmean_kernel<<<(N_NODES + 255) / 256, LD>>>();
    row0_kernel<<<1, 128>>>(W_xa, b_xa, W_r1, b_r1, W_r2, b_r2, out);
    readout_kernel<<<RO_BLOCKS, 128>>>(state, dst, W_r1, b_r1, W_r2, b_r2, out);
}

// round 6
// speedup vs baseline: 2.0244x; 1.4755x over previous
#include <cuda_runtime.h>
#include <cuda_bf16.h>

#define N_NODES 20000
#define N_EDGES 500000
#define BATCH   2
#define D       128
#define H       4
#define L       3
#define HD      (H*D)        // 512
#define LD      (L*D)        // 384
#define F       (L*H + 1)    // 13
#define LH      (L*H)        // 12
#define SLOPE   0.2f

// ---------------- scratch ----------------
__device__ float          g_h[N_NODES * D];
__device__ __nv_bfloat16  g_hpb[N_NODES * HD];
__device__ float g_as[N_NODES * H];
__device__ float g_ad[N_NODES * H];
__device__ float g_xacc[N_NODES * LD];
__device__ float g_ac[LH * N_EDGES];             // TRANSPOSED: [j][e], unnormalized exp(e)
__device__ float g_inv[N_NODES * LH];
__device__ float g_WinT[D * D];
__device__ int   g_deg[N_NODES];
__device__ int   g_rowptr[N_NODES + 1];
__device__ int   g_cursor[N_NODES];
__device__ int   g_csr_src[N_EDGES];
__device__ int   g_csr_eid[N_EDGES];
__device__ float g_colsum[LD];

// ---------------- init / CSR build ----------------
__global__ void zero_kernel() {
    int i = blockIdx.x * blockDim.x + threadIdx.x;
    if (i < N_NODES) g_deg[i] = 0;
    if (i < N_NODES * H) { g_as[i] = 0.f; g_ad[i] = 0.f; }
    if (i < LD) g_colsum[i] = 0.f;
}

__global__ void zero_as_kernel() {
    int i = blockIdx.x * blockDim.x + threadIdx.x;
    if (i < N_NODES * H) { g_as[i] = 0.f; g_ad[i] = 0.f; }
}

__global__ void hist_kernel(const int* __restrict__ dst) {
    int e = blockIdx.x * blockDim.x + threadIdx.x;
    if (e < N_EDGES) atomicAdd(&g_deg[dst[e]], 1);
}

__global__ void __launch_bounds__(1024) scan_kernel() {
    __shared__ int sh[1024];
    const int t = threadIdx.x;
    const int C = (N_NODES + 1023) / 1024;   // 20; threads 0..999 have full chunks
    int start = t * C;
    int deg[20];
    int s = 0;
    if (start + C <= N_NODES) {
        // vectorized: 5x int4 (start is 80B-aligned)
        const int4* p = (const int4*)(g_deg + start);
        #pragma unroll
        for (int q = 0; q < 5; q++) {
            int4 v = p[q];
            deg[q * 4 + 0] = v.x; deg[q * 4 + 1] = v.y;
            deg[q * 4 + 2] = v.z; deg[q * 4 + 3] = v.w;
        }
        #pragma unroll
        for (int q = 0; q < 20; q++) s += deg[q];
    } else {
        for (int i = start; i < N_NODES; i++) { deg[i - start] = g_deg[i]; s += deg[i - start]; }
    }
    sh[t] = s;
    __syncthreads();
    for (int off = 1; off < 1024; off <<= 1) {
        int v = (t >= off) ? sh[t - off] : 0;
        __syncthreads();
        sh[t] += v;
        __syncthreads();
    }
    int run = sh[t] - s;
    int end = min(start + C, N_NODES);
    for (int i = start; i < end; i++) {
        g_rowptr[i] = run;
        g_cursor[i] = run;
        run += deg[i - start];
    }
    if (t == 1023) g_rowptr[N_NODES] = sh[1023];
}

__global__ void fill_kernel(const int* __restrict__ src, const int* __restrict__ dst) {
    int e = blockIdx.x * blockDim.x + threadIdx.x;
    if (e < N_EDGES) {
        int d = dst[e];
        int pos = atomicAdd(&g_cursor[d], 1);
        g_csr_src[pos] = src[e];
        g_csr_eid[pos] = e;
    }
}

__global__ void transpose_win_kernel(const float* __restrict__ W_in) {
    int i = blockIdx.x * blockDim.x + threadIdx.x;
    if (i < D * D) {
        int n = i >> 7, k = i & 127;
        g_WinT[k * D + n] = W_in[n * D + k];
    }
}

// ---------------- tf32 tensor-core GEMM with cp.async pipeline ----------------
__global__ void __launch_bounds__(256) tf32_gemm_kernel(
    const float* __restrict__ A, const float* __restrict__ B,
    float* __restrict__ Cf, const float* __restrict__ bias,
    __nv_bfloat16* __restrict__ hpb,
    const float* __restrict__ a_s, const float* __restrict__ a_d,
    float* __restrict__ as_out, float* __restrict__ ad_out,
    int M, int N)
{
    __shared__ float As[2][128][20];
    __shared__ float Bs[2][16][68];

    const int tid = threadIdx.x;
    const int bm = blockIdx.x * 128, bn = blockIdx.y * 64;
    const int wid = tid >> 5, lane = tid & 31;
    const int wm = (wid >> 1) * 32, wn = (wid & 1) * 32;
    const int g = lane >> 2, tig = lane & 3;

    unsigned As_base = (unsigned)__cvta_generic_to_shared(&As[0][0][0]);
    unsigned Bs_base = (unsigned)__cvta_generic_to_shared(&Bs[0][0][0]);

    const int a_row0 = tid >> 2, a_kc = (tid & 3) * 4;
    const int b_row  = tid >> 4, b_nc = (tid & 15) * 4;

    float c[2][4][4];
    #pragma unroll
    for (int mi = 0; mi < 2; mi++)
        #pragma unroll
        for (int ni = 0; ni < 4; ni++)
            #pragma unroll
            for (int r = 0; r < 4; r++) c[mi][ni][r] = 0.f;

    auto prefetch = [&](int kt, int buf) {
        #pragma unroll
        for (int s = 0; s < 2; s++) {
            int row = a_row0 + s * 64;
            const float* srcp = A + (long)(bm + row) * 128 + kt * 16 + a_kc;
            unsigned dst = As_base + (unsigned)(((buf * 128 + row) * 20 + a_kc) * 4);
            int sz = (bm + row < M) ? 16 : 0;
            asm volatile("cp.async.cg.shared.global [%0], [%1], 16, %2;"
                         :: "r"(dst), "l"(srcp), "r"(sz));
        }
        {
            const float* srcp = B + (long)(kt * 16 + b_row) * N + bn + b_nc;
            unsigned dst = Bs_base + (unsigned)(((buf * 16 + b_row) * 68 + b_nc) * 4);
            asm volatile("cp.async.cg.shared.global [%0], [%1], 16, %2;"
                         :: "r"(dst), "l"(srcp), "r"(16));
        }
        asm volatile("cp.async.commit_group;");
    };

    prefetch(0, 0);

    #pragma unroll
    for (int kt = 0; kt < 8; kt++) {
        const int buf = kt & 1;
        if (kt < 7) {
            prefetch(kt + 1, (kt + 1) & 1);
            asm volatile("cp.async.wait_group 1;");
        } else {
            asm volatile("cp.async.wait_group 0;");
        }
        __syncthreads();

        #pragma unroll
        for (int ks = 0; ks < 2; ks++) {
            const int kb = ks * 8;
            unsigned a[2][4];
            #pragma unroll
            for (int mi = 0; mi < 2; mi++) {
                int r = wm + mi * 16;
                a[mi][0] = __float_as_uint(As[buf][r + g][kb + tig]);
                a[mi][1] = __float_as_uint(As[buf][r + g + 8][kb + tig]);
                a[mi][2] = __float_as_uint(As[buf][r + g][kb + tig + 4]);
                a[mi][3] = __float_as_uint(As[buf][r + g + 8][kb + tig + 4]);
            }
            #pragma unroll
            for (int ni = 0; ni < 4; ni++) {
                unsigned b0 = __float_as_uint(Bs[buf][kb + tig][wn + ni * 8 + g]);
                unsigned b1 = __float_as_uint(Bs[buf][kb + tig + 4][wn + ni * 8 + g]);
                #pragma unroll
                for (int mi = 0; mi < 2; mi++) {
                    asm volatile(
                        "mma.sync.aligned.m16n8k8.row.col.f32.tf32.tf32.f32 "
                        "{%0,%1,%2,%3}, {%4,%5,%6,%7}, {%8,%9}, {%0,%1,%2,%3};"
                        : "+f"(c[mi][ni][0]), "+f"(c[mi][ni][1]),
                          "+f"(c[mi][ni][2]), "+f"(c[mi][ni][3])
                        : "r"(a[mi][0]), "r"(a[mi][1]), "r"(a[mi][2]), "r"(a[mi][3]),
                          "r"(b0), "r"(b1));
                }
            }
        }
        __syncthreads();
    }

    if (Cf) {
        #pragma unroll
        for (int mi = 0; mi < 2; mi++) {
            int row0 = bm + wm + mi * 16 + g;
            int row1 = row0 + 8;
            #pragma unroll
            for (int ni = 0; ni < 4; ni++) {
                int col = bn + wn + ni * 8 + 2 * tig;
                float bx = bias ? bias[col] : 0.f;
                float by = bias ? bias[col + 1] : 0.f;
                if (row0 < M)
                    *(float2*)(Cf + (long)row0 * N + col) =
                        make_float2(c[mi][ni][0] + bx, c[mi][ni][1] + by);
                if (row1 < M)
                    *(float2*)(Cf + (long)row1 * N + col) =
                        make_float2(c[mi][ni][2] + bx, c[mi][ni][3] + by);
            }
        }
    }

    if (hpb) {
        const int head = bn >> 7;
        #pragma unroll
        for (int mi = 0; mi < 2; mi++) {
            int row0 = bm + wm + mi * 16 + g;
            int row1 = row0 + 8;
            float sa0 = 0.f, sd0 = 0.f, sa1 = 0.f, sd1 = 0.f;
            #pragma unroll
            for (int ni = 0; ni < 4; ni++) {
                int col = bn + wn + ni * 8 + 2 * tig;
                float w0s = __ldg(a_s + col), w1s = __ldg(a_s + col + 1);
                float w0d = __ldg(a_d + col), w1d = __ldg(a_d + col + 1);
                sa0 += c[mi][ni][0] * w0s + c[mi][ni][1] * w1s;
                sd0 += c[mi][ni][0] * w0d + c[mi][ni][1] * w1d;
                sa1 += c[mi][ni][2] * w0s + c[mi][ni][3] * w1s;
                sd1 += c[mi][ni][2] * w0d + c[mi][ni][3] * w1d;
                __nv_bfloat162 h0 = __floats2bfloat162_rn(c[mi][ni][0], c[mi][ni][1]);
                __nv_bfloat162 h1 = __floats2bfloat162_rn(c[mi][ni][2], c[mi][ni][3]);
                if (row0 < M) *(__nv_bfloat162*)(hpb + (long)row0 * N + col) = h0;
                if (row1 < M) *(__nv_bfloat162*)(hpb + (long)row1 * N + col) = h1;
            }
            #pragma unroll
            for (int off = 1; off < 4; off <<= 1) {
                sa0 += __shfl_xor_sync(0xffffffffu, sa0, off);
                sd0 += __shfl_xor_sync(0xffffffffu, sd0, off);
                sa1 += __shfl_xor_sync(0xffffffffu, sa1, off);
                sd1 += __shfl_xor_sync(0xffffffffu, sd1, off);
            }
            if (tig == 0) {
                if (row0 < M) {
                    atomicAdd(&as_out[row0 * H + head], sa0);
                    atomicAdd(&ad_out[row0 * H + head], sd0);
                }
                if (row1 < M) {
                    atomicAdd(&as_out[row1 * H + head], sa1);
                    atomicAdd(&ad_out[row1 * H + head], sd1);
                }
            }
        }
    }
}

// ---------------- single-pass softmax-aggregation ----------------
__global__ void __launch_bounds__(128) agg_kernel(const float* __restrict__ b_l, int layer) {
    __shared__ float sh[HD];
    __shared__ int s_src[128];
    __shared__ int s_eid[128];
    __shared__ float4 s_as[128];
    const int n = blockIdx.x;
    const int t = threadIdx.x;
    const int w = t >> 5, ln = t & 31;
    const int start = g_rowptr[n], end = g_rowptr[n + 1];
    const float ad_h = g_ad[n * H + w];
    float* acrow = g_ac + (long)(layer * H + w) * N_EDGES;   // transposed row

    float sum_ex = 0.f;
    float4 acc = make_float4(0.f, 0.f, 0.f, 0.f);

    for (int cs = start; cs < end; cs += 128) {
        int m = min(128, end - cs);
        __syncthreads();
        if (t < m) {
            int s = g_csr_src[cs + t];
            s_src[t] = s;
            s_eid[t] = g_csr_eid[cs + t];
            s_as[t] = *(const float4*)&g_as[s * H];
        }
        __syncthreads();
        #pragma unroll 4
        for (int i = 0; i < m; i++) {
            int src = s_src[i];
            float ev = ((const float*)&s_as[i])[w] + ad_h;
            ev = ev > 0.f ? ev : SLOPE * ev;
            float ex = __expf(ev);
            sum_ex += ex;
            uint2 u = *(const uint2*)(g_hpb + (long)src * HD + w * D + ln * 4);
            float2 f0 = __bfloat1622float2(*reinterpret_cast<__nv_bfloat162*>(&u.x));
            float2 f1 = __bfloat1622float2(*reinterpret_cast<__nv_bfloat162*>(&u.y));
            acc.x += ex * f0.x;
            acc.y += ex * f0.y;
            acc.z += ex * f1.x;
            acc.w += ex * f1.y;
            if (ln == 0) acrow[s_eid[i]] = ex;
        }
    }
    const float inv = 1.0f / (sum_ex + 1e-16f);
    acc.x *= inv; acc.y *= inv; acc.z *= inv; acc.w *= inv;
    if (ln == 0) g_inv[n * LH + layer * H + w] = inv;
    *(float4*)&sh[w * D + ln * 4] = acc;
    __syncthreads();

    float v = 0.25f * (sh[t] + sh[D + t] + sh[2 * D + t] + sh[3 * D + t]) + b_l[t];
    g_xacc[n * LD + layer * D + t] = v;
    g_h[n * D + t] = v > 0.f ? v : SLOPE * v;
}

// ---------------- column means ----------------
__global__ void __launch_bounds__(LD) colmean_kernel() {
    int col = threadIdx.x;
    int n0 = blockIdx.x * 256, n1 = min(n0 + 256, N_NODES);
    float s = 0.f;
    for (int n = n0; n < n1; n++) s += g_xacc[n * LD + col];
    atomicAdd(&g_colsum[col], s);
}

// ---------------- row 0 of output ----------------
__global__ void __launch_bounds__(128) row0_kernel(
    const float* __restrict__ W_xa, const float* __restrict__ b_xa,
    const float* __restrict__ W_r1, const float* __restrict__ b_r1,
    const float* __restrict__ W_r2, const float* __restrict__ b_r2,
    float* __restrict__ out)
{
    __shared__ float smean[LD];
    __shared__ float sxl[F];
    __shared__ float red[128];
    int t = threadIdx.x;
    for (int i = t; i < LD; i += 128) smean[i] = g_colsum[i] * (1.0f / N_NODES);
    __syncthreads();
    if (t < F) {
        float s = b_xa[t];
        for (int k = 0; k < LD; k++) s += smean[k] * W_xa[t * LD + k];
        sxl[t] = s;
    }
    __syncthreads();
    float hsum = b_r1[t];
    #pragma unroll
    for (int j = 0; j < F; j++) hsum += sxl[j] * W_r1[t * F + j];
    hsum = fmaxf(hsum, 0.f);
    red[t] = W_r2[t] * hsum;
    __syncthreads();
    for (int off = 64; off; off >>= 1) {
        if (t < off) red[t] += red[t + off];
        __syncthreads();
    }
    if (t == 0) {
        float v = red[0] + b_r2[0];
        out[0] = v;
        out[N_EDGES + 1] = v;
    }
}

// ---------------- per-edge readout: THREAD per edge, no shuffles ----------------
__global__ void __launch_bounds__(256) readout_kernel(
    const float* __restrict__ state, const int* __restrict__ dst,
    const float* __restrict__ W_r1, const float* __restrict__ b_r1,
    const float* __restrict__ W_r2, const float* __restrict__ b_r2,
    float* __restrict__ out)
{
    __shared__ float sW1[128][16];   // [channel][j] padded; broadcast reads
    __shared__ float sb1[128];
    __shared__ float sW2[128];
    int t = threadIdx.x;
    for (int i = t; i < 128; i += 256) {
        #pragma unroll
        for (int j = 0; j < F; j++) sW1[i][j] = W_r1[i * F + j];
        sb1[i] = b_r1[i];
        sW2[i] = W_r2[i];
    }
    __syncthreads();
    const float br2 = b_r2[0];

    int e = blockIdx.x * 256 + t;
    if (e >= N_EDGES) return;

    // load unnormalized alphas (coalesced: [j][E] layout) and per-dst inverses
    int de = dst[e];
    float4 i0 = *(const float4*)(g_inv + de * LH);
    float4 i1 = *(const float4*)(g_inv + de * LH + 4);
    float4 i2 = *(const float4*)(g_inv + de * LH + 8);
    float a[LH];
    #pragma unroll
    for (int j = 0; j < LH; j++) a[j] = g_ac[(long)j * N_EDGES + e];
    a[0] *= i0.x; a[1] *= i0.y; a[2]  *= i0.z; a[3]  *= i0.w;
    a[4] *= i1.x; a[5] *= i1.y; a[6]  *= i1.z; a[7]  *= i1.w;
    a[8] *= i2.x; a[9] *= i2.y; a[10] *= i2.z; a[11] *= i2.w;

    const float s0 = state[e];
    const float s1 = state[N_EDGES + e];

    float p0 = 0.f, p1 = 0.f;
    #pragma unroll 4
    for (int ch = 0; ch < 128; ch++) {
        float u = sb1[ch];
        const float* wr = sW1[ch];
        #pragma unroll
        for (int j = 0; j < LH; j++) u += a[j] * wr[j + 1];
        float v = wr[0], q = sW2[ch];
        p0 += q * fmaxf(u + s0 * v, 0.f);
        p1 += q * fmaxf(u + s1 * v, 0.f);
    }
    out[1 + e] = p0 + br2;
    out[(N_EDGES + 1) + 1 + e] = p1 + br2;
}

// ---------------- launch ----------------
extern "C" void kernel_launch(void* const* d_in, const int* in_sizes, int n_in,
                              void* d_out, int out_size)
{
    const float* state = (const float*)d_in[0];
    const int*   ei    = (const int*)d_in[1];
    const float* x     = (const float*)d_in[2];
    const float* W_in  = (const float*)d_in[3];
    const float* b_in  = (const float*)d_in[4];
    const float* W_l   = (const float*)d_in[5];
    const float* a_src = (const float*)d_in[6];
    const float* a_dst = (const float*)d_in[7];
    const float* b_l   = (const float*)d_in[8];
    const float* W_xa  = (const float*)d_in[9];
    const float* b_xa  = (const float*)d_in[10];
    const float* W_r1  = (const float*)d_in[11];
    const float* b_r1  = (const float*)d_in[12];
    const float* W_r2  = (const float*)d_in[13];
    const float* b_r2  = (const float*)d_in[14];
    float* out = (float*)d_out;

    const int* src = ei;
    const int* dst = ei + N_EDGES;

    float* hptr;            cudaGetSymbolAddress((void**)&hptr,  g_h);
    __nv_bfloat16* hpbptr;  cudaGetSymbolAddress((void**)&hpbptr, g_hpb);
    float* asptr;           cudaGetSymbolAddress((void**)&asptr, g_as);
    float* adptr;           cudaGetSymbolAddress((void**)&adptr, g_ad);
    float* wintptr;         cudaGetSymbolAddress((void**)&wintptr, g_WinT);

    zero_kernel<<<(N_NODES * H + 255) / 256, 256>>>();
    hist_kernel<<<(N_EDGES + 255) / 256, 256>>>(dst);
    scan_kernel<<<1, 1024>>>();
    fill_kernel<<<(N_EDGES + 255) / 256, 256>>>(src, dst);
    transpose_win_kernel<<<(D * D + 255) / 256, 256>>>(W_in);

    {
        dim3 grid((N_NODES + 127) / 128, D / 64);
        tf32_gemm_kernel<<<grid, 256>>>(x, wintptr, hptr, b_in,
                                        nullptr, nullptr, nullptr, nullptr, nullptr,
                                        N_NODES, D);
    }

    for (int l = 0; l < L; l++) {
        if (l > 0) zero_as_kernel<<<(N_NODES * H + 255) / 256, 256>>>();
        dim3 grid((N_NODES + 127) / 128, HD / 64);
        tf32_gemm_kernel<<<grid, 256>>>(hptr, W_l + (long)l * D * HD,
                                        nullptr, nullptr, hpbptr,
                                        a_src + l * H * D, a_dst + l * H * D,
                                        asptr, adptr,
                                        N_NODES, HD);
        agg_kernel<<<N_NODES, 128>>>(b_l + l * D, l);
    }

    colmean_kernel<<<(N_NODES + 255) / 256, LD>>>();
    row0_kernel<<<1, 128>>>(W_xa, b_xa, W_r1, b_r1, W_r2, b_r2, out);
    readout_kernel<<<(N_EDGES + 255) / 256, 256>>>(state, dst, W_r1, b_r1, W_r2, b_r2, out);
}